// round 9
// baseline (speedup 1.0000x reference)
#include <cuda_runtime.h>
#include <cuda_fp16.h>
#include <cstdint>

#define Bb 8
#define Nn 4096
#define Ff 240
#define Hh 32
#define Ll 240
#define NC (Bb * Hh)   // 256 folded columns
#define KSPLIT 4
#define KCHUNK (Nn / KSPLIT)      // 1024

// Scratch (allocation-free rule: __device__ globals)
__device__ __half g_Ht[NC * Nn];         // H transposed [c][k], fp16, 2 MB
__device__ float  g_P[KSPLIT * Nn * NC]; // split-K partials [kz][c][m], 16 MB

// ===========================================================================
__device__ __forceinline__ void cpasync16(void* dst, const void* src) {
    uint32_t d = (uint32_t)__cvta_generic_to_shared(dst);
    asm volatile("cp.async.cg.shared.global [%0], [%1], 16;\n" :: "r"(d), "l"(src));
}
__device__ __forceinline__ void mma_f16(float c[4], const uint32_t a[4],
                                        const uint32_t b[2]) {
    asm volatile(
        "mma.sync.aligned.m16n8k16.row.col.f32.f16.f16.f32 "
        "{%0,%1,%2,%3}, {%4,%5,%6,%7}, {%8,%9}, {%0,%1,%2,%3};"
        : "+f"(c[0]), "+f"(c[1]), "+f"(c[2]), "+f"(c[3])
        : "r"(a[0]), "r"(a[1]), "r"(a[2]), "r"(a[3]), "r"(b[0]), "r"(b[1]));
}

// ===========================================================================
// K1: g_Ht[b*32+h][m] = fp16( sum_f x[b,m,f] * W1[f,h] )
// x tile staged via cp.async (coalesced), stride 244 pad (conflict-free).
// CTA: 64 rows x 1 batch; block (8,32); grid (64, 8).
// ===========================================================================
#define XSTR 244
#define K1_SMEM ((64 * XSTR + Ff * Hh) * 4)   // 93184 B

__global__ __launch_bounds__(256) void k1_xw1(const float* __restrict__ x,
                                              const float* __restrict__ W1) {
    extern __shared__ float k1sm[];
    float* xs  = k1sm;              // [64][XSTR]
    float* W1s = k1sm + 64 * XSTR;  // [Ff][Hh] linear f*32+h

    const int tx = threadIdx.x, ty = threadIdx.y;
    const int tid = ty * 8 + tx;
    const int b  = blockIdx.y;
    const int n0 = blockIdx.x * 64;

    // stage x tile: 64 rows x 240 floats, 16B chunks, coalesced
    const float* xbase = x + ((size_t)b * Nn + n0) * Ff;
    #pragma unroll
    for (int t = 0; t < 15; t++) {
        int c = tid + t * 256;
        int row = c / 60, f4 = c % 60;
        cpasync16(xs + row * XSTR + f4 * 4, xbase + (size_t)row * Ff + f4 * 4);
    }
    asm volatile("cp.async.commit_group;\n");
    for (int i = tid; i < Ff * Hh; i += 256) W1s[i] = W1[i];
    asm volatile("cp.async.wait_group 0;\n");
    __syncthreads();

    const int rowL = ty * 2;
    const int h0   = tx * 4;

    float acc[2][4];
    #pragma unroll
    for (int r = 0; r < 2; r++)
        #pragma unroll
        for (int h = 0; h < 4; h++) acc[r][h] = 0.f;

    #pragma unroll 4
    for (int f4 = 0; f4 < Ff / 4; f4++) {
        int f = f4 * 4;
        float4 wa = *reinterpret_cast<const float4*>(&W1s[(f + 0) * Hh + h0]);
        float4 wb = *reinterpret_cast<const float4*>(&W1s[(f + 1) * Hh + h0]);
        float4 wc = *reinterpret_cast<const float4*>(&W1s[(f + 2) * Hh + h0]);
        float4 wd = *reinterpret_cast<const float4*>(&W1s[(f + 3) * Hh + h0]);
        #pragma unroll
        for (int r = 0; r < 2; r++) {
            float4 xv = *reinterpret_cast<const float4*>(
                &xs[(rowL + r) * XSTR + f4 * 4]);
            acc[r][0] += xv.x * wa.x + xv.y * wb.x + xv.z * wc.x + xv.w * wd.x;
            acc[r][1] += xv.x * wa.y + xv.y * wb.y + xv.z * wc.y + xv.w * wd.y;
            acc[r][2] += xv.x * wa.z + xv.y * wb.z + xv.z * wc.z + xv.w * wd.z;
            acc[r][3] += xv.x * wa.w + xv.y * wb.w + xv.z * wc.w + xv.w * wd.w;
        }
    }
    #pragma unroll
    for (int j = 0; j < 4; j++) {
        __half2 v = __floats2half2_rn(acc[0][j], acc[1][j]);
        *reinterpret_cast<__half2*>(
            &g_Ht[(size_t)(b * Hh + h0 + j) * Nn + n0 + rowL]) = v;
    }
}

// ===========================================================================
// K2: split-K fp16 mma.sync GEMM. BM=128, BN=256, BK=32; 512 thr, 16 warps.
// A: fp32 gmem -> reg prefetch -> cvt -> STS fp16. B: cp.async fp16 from g_Ht.
// 3-stage ring, 1 syncthreads/iter.
// ===========================================================================
#define K2_BM 128
#define K2_BK 32
#define K2_NIT (KCHUNK / K2_BK)    // 32
#define HSTR 40                    // halves per padded row (80 B)
#define A_ST_B (K2_BM * HSTR * 2)  // 10240 B
#define B_ST_B (NC * HSTR * 2)     // 20480 B
#define STAGE_B (A_ST_B + B_ST_B)  // 30720 B
#define K2_SMEM (3 * STAGE_B)      // 92160 B

__global__ __launch_bounds__(512) void k2_tc(const float* __restrict__ A) {
    extern __shared__ char smem[];

    const int tid  = threadIdx.x;
    const int warp = tid >> 5;
    const int lane = tid & 31;
    const int bm   = blockIdx.x * K2_BM;
    const int kbase = blockIdx.y * KCHUNK;

    const int wm = (warp & 3) * 32;
    const int wn = (warp >> 2) * 64;
    const int r  = lane >> 2;
    const int cc = lane & 3;

    // A prefetch mapping: 2 chunks (float4) per thread
    const int a_row = tid >> 3;          // 0..63 (+64)
    const int a_f4  = tid & 7;           // 0..7
    // B cp.async mapping: 2 chunks (16B = 8 halves) per thread
    const int b_row = tid >> 2;          // 0..127 (+128)
    const int b_q   = tid & 3;           // 0..3

    auto ldgA = [&](int it, float4 pr[2]) {
        int kcol = kbase + it * K2_BK;
        #pragma unroll
        for (int t = 0; t < 2; t++) {
            int row = a_row + t * 64;
            pr[t] = *reinterpret_cast<const float4*>(
                A + (size_t)(bm + row) * Nn + kcol + a_f4 * 4);
        }
    };
    auto stsA = [&](int it, const float4 pr[2]) {
        __half* ab = reinterpret_cast<__half*>(smem + (it % 3) * STAGE_B);
        #pragma unroll
        for (int t = 0; t < 2; t++) {
            int row = a_row + t * 64;
            __half2 h0 = __floats2half2_rn(pr[t].x, pr[t].y);
            __half2 h1 = __floats2half2_rn(pr[t].z, pr[t].w);
            uint2 u;
            u.x = *reinterpret_cast<uint32_t*>(&h0);
            u.y = *reinterpret_cast<uint32_t*>(&h1);
            *reinterpret_cast<uint2*>(&ab[row * HSTR + a_f4 * 4]) = u;
        }
    };
    auto loadB = [&](int it) {
        char* bb = smem + (it % 3) * STAGE_B + A_ST_B;
        int kcol = kbase + it * K2_BK;
        #pragma unroll
        for (int t = 0; t < 2; t++) {
            int row = b_row + t * 128;
            cpasync16(bb + row * (HSTR * 2) + b_q * 16,
                      g_Ht + (size_t)row * Nn + kcol + b_q * 8);
        }
    };

    float acc[2][8][4];
    #pragma unroll
    for (int mi = 0; mi < 2; mi++)
        #pragma unroll
        for (int ni = 0; ni < 8; ni++)
            #pragma unroll
            for (int q = 0; q < 4; q++) acc[mi][ni][q] = 0.f;

    // prologue
    float4 preg[2][2];
    ldgA(0, preg[0]);
    ldgA(1, preg[1]);
    stsA(0, preg[0]);
    loadB(0);
    asm volatile("cp.async.commit_group;\n");
    stsA(1, preg[1]);
    loadB(1);
    asm volatile("cp.async.commit_group;\n");
    ldgA(2, preg[0]);

    for (int i = 0; i < K2_NIT; i++) {
        asm volatile("cp.async.wait_group 1;\n");
        __syncthreads();

        if (i + 2 < K2_NIT) {
            stsA(i + 2, preg[i & 1]);
            loadB(i + 2);
        }
        if (i + 3 < K2_NIT) ldgA(i + 3, preg[(i + 1) & 1]);
        asm volatile("cp.async.commit_group;\n");

        const __half* as = reinterpret_cast<const __half*>(
            smem + (i % 3) * STAGE_B);
        const __half* bs = reinterpret_cast<const __half*>(
            smem + (i % 3) * STAGE_B + A_ST_B);

        #pragma unroll
        for (int ks = 0; ks < 2; ks++) {
            const int k0 = ks * 16;
            uint32_t af[2][4];
            #pragma unroll
            for (int mi = 0; mi < 2; mi++) {
                const __half* ap = as + (wm + mi * 16 + r) * HSTR + k0 + 2 * cc;
                af[mi][0] = *reinterpret_cast<const uint32_t*>(ap);
                af[mi][1] = *reinterpret_cast<const uint32_t*>(ap + 8 * HSTR);
                af[mi][2] = *reinterpret_cast<const uint32_t*>(ap + 8);
                af[mi][3] = *reinterpret_cast<const uint32_t*>(ap + 8 * HSTR + 8);
            }
            uint32_t bf[8][2];
            #pragma unroll
            for (int ni = 0; ni < 8; ni++) {
                const __half* bp = bs + (wn + ni * 8 + r) * HSTR + k0 + 2 * cc;
                bf[ni][0] = *reinterpret_cast<const uint32_t*>(bp);
                bf[ni][1] = *reinterpret_cast<const uint32_t*>(bp + 8);
            }
            #pragma unroll
            for (int mi = 0; mi < 2; mi++)
                #pragma unroll
                for (int ni = 0; ni < 8; ni++)
                    mma_f16(acc[mi][ni], af[mi], bf[ni]);
        }
    }

    // epilogue: raw partials, c-major [c][m]
    float* P = g_P + (size_t)blockIdx.y * Nn * NC;
    #pragma unroll
    for (int mi = 0; mi < 2; mi++) {
        #pragma unroll
        for (int ni = 0; ni < 8; ni++) {
            int gm = bm + wm + mi * 16 + r;
            int gc = wn + ni * 8 + cc * 2;
            P[(size_t)gc * Nn + gm]           = acc[mi][ni][0];
            P[(size_t)(gc + 1) * Nn + gm]     = acc[mi][ni][1];
            P[(size_t)gc * Nn + gm + 8]       = acc[mi][ni][2];
            P[(size_t)(gc + 1) * Nn + gm + 8] = acc[mi][ni][3];
        }
    }
}

// ===========================================================================
// K3: out[b,n,l] = sum_h relu(sum_z Pz[b*32+h][n] + b1[h]) * W2[h,l] + b2[l]
// ===========================================================================
__global__ __launch_bounds__(256) void k3_out(const float* __restrict__ b1,
                                              const float* __restrict__ W2,
                                              const float* __restrict__ b2,
                                              float* __restrict__ out) {
    __shared__ float Rs[32][Hh];
    int b  = blockIdx.y;
    int n0 = blockIdx.x * 32;
    int tid = threadIdx.x;

    for (int i = tid; i < 32 * Hh; i += 256) {
        int h = i >> 5, rr = i & 31;   // coalesced along n
        size_t idx = (size_t)(b * Hh + h) * Nn + n0 + rr;
        float s = g_P[idx]
                + g_P[idx + (size_t)1 * Nn * NC]
                + g_P[idx + (size_t)2 * Nn * NC]
                + g_P[idx + (size_t)3 * Nn * NC];
        Rs[rr][h] = fmaxf(s + b1[h], 0.f);
    }
    __syncthreads();

    if (tid < Ll) {
        float w2r[Hh];
        #pragma unroll
        for (int h = 0; h < Hh; h++) w2r[h] = W2[h * Ll + tid];
        float bias = b2[tid];
        #pragma unroll 4
        for (int rr = 0; rr < 32; rr++) {
            float acc = bias;
            #pragma unroll
            for (int h = 0; h < Hh; h++) acc += Rs[rr][h] * w2r[h];
            out[((size_t)b * Nn + n0 + rr) * Ll + tid] = acc;
        }
    }
}

// ===========================================================================
extern "C" void kernel_launch(void* const* d_in, const int* in_sizes, int n_in,
                              void* d_out, int out_size) {
    const float* x  = (const float*)d_in[0];
    const float* a  = (const float*)d_in[1];
    const float* W1 = (const float*)d_in[2];
    const float* b1 = (const float*)d_in[3];
    const float* W2 = (const float*)d_in[4];
    const float* b2 = (const float*)d_in[5];
    float* out = (float*)d_out;

    cudaFuncSetAttribute(k1_xw1, cudaFuncAttributeMaxDynamicSharedMemorySize,
                         K1_SMEM);
    dim3 g1(Nn / 64, Bb), t1(8, 32);
    k1_xw1<<<g1, t1, K1_SMEM>>>(x, W1);

    cudaFuncSetAttribute(k2_tc, cudaFuncAttributeMaxDynamicSharedMemorySize,
                         K2_SMEM);
    dim3 g2(Nn / K2_BM, KSPLIT);
    k2_tc<<<g2, 512, K2_SMEM>>>(a);

    dim3 g3(Nn / 32, Bb);
    k3_out<<<g3, 256>>>(b1, W2, b2, out);
}

// round 10
// speedup vs baseline: 1.4219x; 1.4219x over previous
#include <cuda_runtime.h>
#include <cuda_fp16.h>
#include <cstdint>

#define Bb 8
#define Nn 4096
#define Ff 240
#define Hh 32
#define Ll 240
#define NC (Bb * Hh)   // 256 folded columns
#define KSPLIT 2
#define KCHUNK (Nn / KSPLIT)      // 2048

// Scratch (allocation-free rule: __device__ globals)
__device__ __half g_a16[(size_t)Nn * Nn];   // fp16 copy of a, 32 MB
__device__ __half g_Ht[NC * Nn];            // H transposed [c][k], fp16, 2 MB
__device__ float  g_P[KSPLIT * Nn * NC];    // split-K partials [kz][c][m], 8 MB

// ===========================================================================
__device__ __forceinline__ void cpasync16(void* dst, const void* src) {
    uint32_t d = (uint32_t)__cvta_generic_to_shared(dst);
    asm volatile("cp.async.cg.shared.global [%0], [%1], 16;\n" :: "r"(d), "l"(src));
}
__device__ __forceinline__ void mma_f16(float c[4], const uint32_t a[4],
                                        const uint32_t b[2]) {
    asm volatile(
        "mma.sync.aligned.m16n8k16.row.col.f32.f16.f16.f32 "
        "{%0,%1,%2,%3}, {%4,%5,%6,%7}, {%8,%9}, {%0,%1,%2,%3};"
        : "+f"(c[0]), "+f"(c[1]), "+f"(c[2]), "+f"(c[3])
        : "r"(a[0]), "r"(a[1]), "r"(a[2]), "r"(a[3]), "r"(b[0]), "r"(b[1]));
}

// ===========================================================================
// K0: g_a16 = (half)a. Pure stream, float4 in / half2x4 out.
// ===========================================================================
__global__ __launch_bounds__(256) void k0_cvt(const float* __restrict__ a) {
    size_t i = ((size_t)blockIdx.x * 256 + threadIdx.x) * 8;
    float4 v0 = *reinterpret_cast<const float4*>(a + i);
    float4 v1 = *reinterpret_cast<const float4*>(a + i + 4);
    __half2 h[4];
    h[0] = __floats2half2_rn(v0.x, v0.y);
    h[1] = __floats2half2_rn(v0.z, v0.w);
    h[2] = __floats2half2_rn(v1.x, v1.y);
    h[3] = __floats2half2_rn(v1.z, v1.w);
    *reinterpret_cast<uint4*>(&g_a16[i]) = *reinterpret_cast<uint4*>(h);
}

// ===========================================================================
// K1 (R7 shape, fp16 out): g_Ht[b*32+h][m] = fp16( sum_f x[b,m,f] * W1[f,h] )
// 2 rows x 4 h per thread; block (8,32); grid (64, 8) = 512 CTAs.
// ===========================================================================
__global__ __launch_bounds__(256) void k1_xw1(const float* __restrict__ x,
                                              const float* __restrict__ W1) {
    __shared__ float W1s[Ff][Hh];
    int tid = threadIdx.y * 8 + threadIdx.x;
    for (int i = tid; i < Ff * Hh; i += 256)
        W1s[i / Hh][i % Hh] = W1[i];
    __syncthreads();

    int b    = blockIdx.y;
    int row0 = blockIdx.x * 64 + threadIdx.y * 2;
    int h0   = threadIdx.x * 4;
    const float* xr = x + ((size_t)b * Nn + row0) * Ff;

    float acc[2][4];
    #pragma unroll
    for (int r = 0; r < 2; r++)
        #pragma unroll
        for (int h = 0; h < 4; h++) acc[r][h] = 0.f;

    #pragma unroll 4
    for (int f4 = 0; f4 < Ff / 4; f4++) {
        int f = f4 * 4;
        float4 wa = *reinterpret_cast<const float4*>(&W1s[f + 0][h0]);
        float4 wb = *reinterpret_cast<const float4*>(&W1s[f + 1][h0]);
        float4 wc = *reinterpret_cast<const float4*>(&W1s[f + 2][h0]);
        float4 wd = *reinterpret_cast<const float4*>(&W1s[f + 3][h0]);
        #pragma unroll
        for (int r = 0; r < 2; r++) {
            float4 xv = *reinterpret_cast<const float4*>(xr + (size_t)r * Ff + f);
            acc[r][0] += xv.x * wa.x + xv.y * wb.x + xv.z * wc.x + xv.w * wd.x;
            acc[r][1] += xv.x * wa.y + xv.y * wb.y + xv.z * wc.y + xv.w * wd.y;
            acc[r][2] += xv.x * wa.z + xv.y * wb.z + xv.z * wc.z + xv.w * wd.z;
            acc[r][3] += xv.x * wa.w + xv.y * wb.w + xv.z * wc.w + xv.w * wd.w;
        }
    }
    #pragma unroll
    for (int j = 0; j < 4; j++) {
        __half2 v = __floats2half2_rn(acc[0][j], acc[1][j]);
        *reinterpret_cast<__half2*>(
            &g_Ht[(size_t)(b * Hh + h0 + j) * Nn + row0]) = v;
    }
}

// ===========================================================================
// K2: pure-fp16 split-K mma.sync GEMM.
// BM=128, BN=128, BK=32; 512 thr, 16 warps (4m x 4n), warp tile 32x32.
// 4-stage cp.async ring, 1 syncthreads/iter, zero conversions in kernel.
// grid (Nn/128, NC/128, KSPLIT) = (32, 2, 2) = 128 CTAs.
// ===========================================================================
#define K2_BM 128
#define K2_BN 128
#define K2_BK 32
#define K2_NIT (KCHUNK / K2_BK)    // 64
#define HSTR 40                    // halves per padded row (80 B)
#define A_ST_B (K2_BM * HSTR * 2)  // 10240 B
#define B_ST_B (K2_BN * HSTR * 2)  // 10240 B
#define STAGE_B (A_ST_B + B_ST_B)  // 20480 B
#define STAGES 4
#define K2_SMEM (STAGES * STAGE_B) // 81920 B

__global__ __launch_bounds__(512) void k2_tc() {
    extern __shared__ char smem[];

    const int tid  = threadIdx.x;
    const int warp = tid >> 5;
    const int lane = tid & 31;
    const int bm   = blockIdx.x * K2_BM;
    const int bnoff = blockIdx.y * K2_BN;
    const int kbase = blockIdx.z * KCHUNK;

    const int wm = (warp & 3) * 32;
    const int wn = (warp >> 2) * 32;
    const int r  = lane >> 2;
    const int cc = lane & 3;

    // cp.async mapping: 1 chunk (16B = 8 halves) per thread per operand
    const int ld_row = tid >> 2;         // 0..127
    const int ld_q   = tid & 3;          // 0..3  (k-offset *8 halves)

    auto load_tile = [&](int it) {
        char* ab = smem + (it % STAGES) * STAGE_B;
        char* bb = ab + A_ST_B;
        int kcol = kbase + it * K2_BK;
        cpasync16(ab + ld_row * (HSTR * 2) + ld_q * 16,
                  g_a16 + (size_t)(bm + ld_row) * Nn + kcol + ld_q * 8);
        cpasync16(bb + ld_row * (HSTR * 2) + ld_q * 16,
                  g_Ht + (size_t)(bnoff + ld_row) * Nn + kcol + ld_q * 8);
    };

    float acc[2][4][4];
    #pragma unroll
    for (int mi = 0; mi < 2; mi++)
        #pragma unroll
        for (int ni = 0; ni < 4; ni++)
            #pragma unroll
            for (int q = 0; q < 4; q++) acc[mi][ni][q] = 0.f;

    // prologue: stages 0..2
    load_tile(0); asm volatile("cp.async.commit_group;\n");
    load_tile(1); asm volatile("cp.async.commit_group;\n");
    load_tile(2); asm volatile("cp.async.commit_group;\n");

    for (int i = 0; i < K2_NIT; i++) {
        asm volatile("cp.async.wait_group 2;\n");
        __syncthreads();
        if (i + 3 < K2_NIT) load_tile(i + 3);
        asm volatile("cp.async.commit_group;\n");

        const __half* as = reinterpret_cast<const __half*>(
            smem + (i % STAGES) * STAGE_B);
        const __half* bs = reinterpret_cast<const __half*>(
            smem + (i % STAGES) * STAGE_B + A_ST_B);

        #pragma unroll
        for (int ks = 0; ks < 2; ks++) {
            const int k0 = ks * 16;
            uint32_t af[2][4];
            #pragma unroll
            for (int mi = 0; mi < 2; mi++) {
                const __half* ap = as + (wm + mi * 16 + r) * HSTR + k0 + 2 * cc;
                af[mi][0] = *reinterpret_cast<const uint32_t*>(ap);
                af[mi][1] = *reinterpret_cast<const uint32_t*>(ap + 8 * HSTR);
                af[mi][2] = *reinterpret_cast<const uint32_t*>(ap + 8);
                af[mi][3] = *reinterpret_cast<const uint32_t*>(ap + 8 * HSTR + 8);
            }
            uint32_t bf[4][2];
            #pragma unroll
            for (int ni = 0; ni < 4; ni++) {
                const __half* bp = bs + (wn + ni * 8 + r) * HSTR + k0 + 2 * cc;
                bf[ni][0] = *reinterpret_cast<const uint32_t*>(bp);
                bf[ni][1] = *reinterpret_cast<const uint32_t*>(bp + 8);
            }
            #pragma unroll
            for (int mi = 0; mi < 2; mi++)
                #pragma unroll
                for (int ni = 0; ni < 4; ni++)
                    mma_f16(acc[mi][ni], af[mi], bf[ni]);
        }
    }

    // epilogue: raw partials, c-major [c][m]
    float* P = g_P + (size_t)blockIdx.z * Nn * NC;
    #pragma unroll
    for (int mi = 0; mi < 2; mi++) {
        #pragma unroll
        for (int ni = 0; ni < 4; ni++) {
            int gm = bm + wm + mi * 16 + r;
            int gc = bnoff + wn + ni * 8 + cc * 2;
            P[(size_t)gc * Nn + gm]           = acc[mi][ni][0];
            P[(size_t)(gc + 1) * Nn + gm]     = acc[mi][ni][1];
            P[(size_t)gc * Nn + gm + 8]       = acc[mi][ni][2];
            P[(size_t)(gc + 1) * Nn + gm + 8] = acc[mi][ni][3];
        }
    }
}

// ===========================================================================
// K3: out[b,n,l] = sum_h relu(sum_z Pz[b*32+h][n] + b1[h]) * W2[h,l] + b2[l]
// ===========================================================================
__global__ __launch_bounds__(256) void k3_out(const float* __restrict__ b1,
                                              const float* __restrict__ W2,
                                              const float* __restrict__ b2,
                                              float* __restrict__ out) {
    __shared__ float Rs[32][Hh];
    int b  = blockIdx.y;
    int n0 = blockIdx.x * 32;
    int tid = threadIdx.x;

    for (int i = tid; i < 32 * Hh; i += 256) {
        int h = i >> 5, rr = i & 31;   // coalesced along n
        size_t idx = (size_t)(b * Hh + h) * Nn + n0 + rr;
        float s = g_P[idx] + g_P[idx + (size_t)Nn * NC];
        Rs[rr][h] = fmaxf(s + b1[h], 0.f);
    }
    __syncthreads();

    if (tid < Ll) {
        float w2r[Hh];
        #pragma unroll
        for (int h = 0; h < Hh; h++) w2r[h] = W2[h * Ll + tid];
        float bias = b2[tid];
        #pragma unroll 4
        for (int rr = 0; rr < 32; rr++) {
            float acc = bias;
            #pragma unroll
            for (int h = 0; h < Hh; h++) acc += Rs[rr][h] * w2r[h];
            out[((size_t)b * Nn + n0 + rr) * Ll + tid] = acc;
        }
    }
}

// ===========================================================================
extern "C" void kernel_launch(void* const* d_in, const int* in_sizes, int n_in,
                              void* d_out, int out_size) {
    const float* x  = (const float*)d_in[0];
    const float* a  = (const float*)d_in[1];
    const float* W1 = (const float*)d_in[2];
    const float* b1 = (const float*)d_in[3];
    const float* W2 = (const float*)d_in[4];
    const float* b2 = (const float*)d_in[5];
    float* out = (float*)d_out;

    k0_cvt<<<(Nn * (size_t)Nn) / (256 * 8), 256>>>(a);

    dim3 g1(Nn / 64, Bb), t1(8, 32);
    k1_xw1<<<g1, t1>>>(x, W1);

    cudaFuncSetAttribute(k2_tc, cudaFuncAttributeMaxDynamicSharedMemorySize,
                         K2_SMEM);
    dim3 g2(Nn / K2_BM, NC / K2_BN, KSPLIT);
    k2_tc<<<g2, 512, K2_SMEM>>>();

    dim3 g3(Nn / 32, Bb);
    k3_out<<<g3, 256>>>(b1, W2, b2, out);
}